// round 13
// baseline (speedup 1.0000x reference)
#include <cuda_runtime.h>
#include <cstdint>

// VQ: argmin_k ||z_n - e_k||^2 -> z_q + indices. Scalar FFMA2 path.
// R11 vs R10 (262us, issue=36%) / R3 (230us, fma=53%):
//   binder identified: 2 warps/SMSP + ~90 non-FMA issues per code pair ->
//   issue stalls cap fma ~50%. Fix: RPT=1 (z row = 64 regs, ~96 total) ->
//   CTA=64 (2 warps, staging shared), grid=1024 (98.8% SM balance),
//   __launch_bounds__(64,6) -> 6 CTAs/SM = 3 warps/SMSP -> FMA pipe binds.
// Numerics byte-exact vs rel_err=0.0 kernels (4-acc tree, unfused z2/e2,
// d = fl(fmaf(-2,dot,z2)) + e2, tie keeps lowest index).

#define DIMS 64
#define TK   128     // codes per smem tile
#define CTA  64
#define RPT  1

__device__ float g_e2[8192];

typedef unsigned long long u64;

__device__ __forceinline__ u64 fma2(u64 a, u64 b, u64 c) {
    u64 r;
    asm("fma.rn.f32x2 %0, %1, %2, %3;" : "=l"(r) : "l"(a), "l"(b), "l"(c));
    return r;
}
__device__ __forceinline__ u64 add2(u64 a, u64 b) {
    u64 r;
    asm("add.rn.f32x2 %0, %1, %2;" : "=l"(r) : "l"(a), "l"(b));
    return r;
}
__device__ __forceinline__ void unpack2(u64 v, float& lo, float& hi) {
    asm("mov.b64 {%0, %1}, %2;" : "=f"(lo), "=f"(hi) : "l"(v));
}

// ---- pass 1: ||e_k||^2 (reference order: square then add) --------------------
__global__ void e2_kernel(const float* __restrict__ cb, int K) {
    int k = blockIdx.x * blockDim.x + threadIdx.x;
    if (k >= K) return;
    const float4* row = reinterpret_cast<const float4*>(cb + (size_t)k * DIMS);
    float s = 0.f;
#pragma unroll
    for (int i = 0; i < DIMS / 4; i++) {
        float4 v = row[i];
        s = __fadd_rn(s, __fmul_rn(v.x, v.x));
        s = __fadd_rn(s, __fmul_rn(v.y, v.y));
        s = __fadd_rn(s, __fmul_rn(v.z, v.z));
        s = __fadd_rn(s, __fmul_rn(v.w, v.w));
    }
    g_e2[k] = s;
}

// ---- pass 2: main VQ ----------------------------------------------------------
__global__ __launch_bounds__(CTA, 6)
void vq_kernel(const float* __restrict__ z, const float* __restrict__ cb,
               int N, int K, float* __restrict__ out_q, float* __restrict__ out_idx)
{
    __shared__ float s_tile[TK * DIMS];
    __shared__ float s_e2[TK];

    const int n0 = blockIdx.x * CTA + threadIdx.x;
    const bool act = (n0 < N);

    // z row in packed f32x2 registers (+ unfused ||z||^2, reference order)
    u64 zr[DIMS / 2];
    float z2 = 0.f;
    {
        const ulonglong2* zp = reinterpret_cast<const ulonglong2*>(z + (size_t)(act ? n0 : 0) * DIMS);
#pragma unroll
        for (int i = 0; i < DIMS / 4; i++) {
            ulonglong2 a = zp[i];
            zr[2 * i + 0] = a.x;
            zr[2 * i + 1] = a.y;
            float x, y;
            unpack2(a.x, x, y);
            z2 = __fadd_rn(z2, __fmul_rn(x, x)); z2 = __fadd_rn(z2, __fmul_rn(y, y));
            unpack2(a.y, x, y);
            z2 = __fadd_rn(z2, __fmul_rn(x, x)); z2 = __fadd_rn(z2, __fmul_rn(y, y));
        }
    }

    float best = 3.4e38f;
    int   bidx = 0;

    for (int t0 = 0; t0 < K; t0 += TK) {
        __syncthreads();
        {   // stage codebook tile (coalesced float4) + e2 slice; 2 warps share
            const float4* cp = reinterpret_cast<const float4*>(cb + (size_t)t0 * DIMS);
            float4* sp = reinterpret_cast<float4*>(s_tile);
#pragma unroll 8
            for (int i = threadIdx.x; i < TK * DIMS / 4; i += CTA) sp[i] = cp[i];
            s_e2[threadIdx.x]      = g_e2[t0 + threadIdx.x];
            s_e2[threadIdx.x + 64] = g_e2[t0 + threadIdx.x + 64];
        }
        __syncthreads();

#pragma unroll 4
        for (int kk = 0; kk < TK; kk++) {
            const ulonglong2* cs =
                reinterpret_cast<const ulonglong2*>(s_tile + kk * DIMS);
            const float e2  = s_e2[kk];
            const int  kidx = t0 + kk;

            u64 a0 = 0, a1 = 0, a2 = 0, a3 = 0;   // 4-acc tree (as R1)
#pragma unroll
            for (int j = 0; j < DIMS / 8; j++) {
                ulonglong2 c0 = cs[2 * j + 0];
                ulonglong2 c1 = cs[2 * j + 1];
                a0 = fma2(zr[4 * j + 0], c0.x, a0);
                a1 = fma2(zr[4 * j + 1], c0.y, a1);
                a2 = fma2(zr[4 * j + 2], c1.x, a2);
                a3 = fma2(zr[4 * j + 3], c1.y, a3);
            }
            u64 s = add2(add2(a0, a1), add2(a2, a3));
            float lo, hi;
            unpack2(s, lo, hi);
            float dot = __fadd_rn(lo, hi);
            float d = __fadd_rn(__fmaf_rn(-2.f, dot, z2), e2);
            bool lt = d < best;
            best = lt ? d    : best;
            bidx = lt ? kidx : bidx;
        }
    }

    if (act) {
        const float4* crow = reinterpret_cast<const float4*>(cb + (size_t)bidx * DIMS);
        float4* orow = reinterpret_cast<float4*>(out_q + (size_t)n0 * DIMS);
#pragma unroll
        for (int i = 0; i < DIMS / 4; i++) orow[i] = crow[i];
        if (out_idx) out_idx[n0] = (float)bidx;
    }
}

extern "C" void kernel_launch(void* const* d_in, const int* in_sizes, int n_in,
                              void* d_out, int out_size) {
    const float* z  = (const float*)d_in[0];
    const float* cb = (const float*)d_in[1];
    const int N = in_sizes[0] / DIMS;
    const int K = in_sizes[1] / DIMS;
    float* out = (float*)d_out;

    float* out_idx = nullptr;
    if ((long long)out_size >= (long long)N * DIMS + N)
        out_idx = out + (size_t)N * DIMS;

    e2_kernel<<<(K + 255) / 256, 256>>>(cb, K);
    vq_kernel<<<(N + CTA - 1) / CTA, CTA>>>(z, cb, N, K, out, out_idx);
}

// round 14
// speedup vs baseline: 1.0020x; 1.0020x over previous
#include <cuda_runtime.h>
#include <cstdint>

// VQ: argmin_k ||z_n - e_k||^2 -> z_q + indices. Scalar FFMA2 path.
// R11 vs R10 (262us, issue=36%) / R3 (230us, fma=53%):
//   binder identified: 2 warps/SMSP + ~90 non-FMA issues per code pair ->
//   issue stalls cap fma ~50%. Fix: RPT=1 (z row = 64 regs, ~96 total) ->
//   CTA=64 (2 warps, staging shared), grid=1024 (98.8% SM balance),
//   __launch_bounds__(64,6) -> 6 CTAs/SM = 3 warps/SMSP -> FMA pipe binds.
// Numerics byte-exact vs rel_err=0.0 kernels (4-acc tree, unfused z2/e2,
// d = fl(fmaf(-2,dot,z2)) + e2, tie keeps lowest index).

#define DIMS 64
#define TK   128     // codes per smem tile
#define CTA  64
#define RPT  1

__device__ float g_e2[8192];

typedef unsigned long long u64;

__device__ __forceinline__ u64 fma2(u64 a, u64 b, u64 c) {
    u64 r;
    asm("fma.rn.f32x2 %0, %1, %2, %3;" : "=l"(r) : "l"(a), "l"(b), "l"(c));
    return r;
}
__device__ __forceinline__ u64 add2(u64 a, u64 b) {
    u64 r;
    asm("add.rn.f32x2 %0, %1, %2;" : "=l"(r) : "l"(a), "l"(b));
    return r;
}
__device__ __forceinline__ void unpack2(u64 v, float& lo, float& hi) {
    asm("mov.b64 {%0, %1}, %2;" : "=f"(lo), "=f"(hi) : "l"(v));
}

// ---- pass 1: ||e_k||^2 (reference order: square then add) --------------------
__global__ void e2_kernel(const float* __restrict__ cb, int K) {
    int k = blockIdx.x * blockDim.x + threadIdx.x;
    if (k >= K) return;
    const float4* row = reinterpret_cast<const float4*>(cb + (size_t)k * DIMS);
    float s = 0.f;
#pragma unroll
    for (int i = 0; i < DIMS / 4; i++) {
        float4 v = row[i];
        s = __fadd_rn(s, __fmul_rn(v.x, v.x));
        s = __fadd_rn(s, __fmul_rn(v.y, v.y));
        s = __fadd_rn(s, __fmul_rn(v.z, v.z));
        s = __fadd_rn(s, __fmul_rn(v.w, v.w));
    }
    g_e2[k] = s;
}

// ---- pass 2: main VQ ----------------------------------------------------------
__global__ __launch_bounds__(CTA, 6)
void vq_kernel(const float* __restrict__ z, const float* __restrict__ cb,
               int N, int K, float* __restrict__ out_q, float* __restrict__ out_idx)
{
    __shared__ float s_tile[TK * DIMS];
    __shared__ float s_e2[TK];

    const int n0 = blockIdx.x * CTA + threadIdx.x;
    const bool act = (n0 < N);

    // z row in packed f32x2 registers (+ unfused ||z||^2, reference order)
    u64 zr[DIMS / 2];
    float z2 = 0.f;
    {
        const ulonglong2* zp = reinterpret_cast<const ulonglong2*>(z + (size_t)(act ? n0 : 0) * DIMS);
#pragma unroll
        for (int i = 0; i < DIMS / 4; i++) {
            ulonglong2 a = zp[i];
            zr[2 * i + 0] = a.x;
            zr[2 * i + 1] = a.y;
            float x, y;
            unpack2(a.x, x, y);
            z2 = __fadd_rn(z2, __fmul_rn(x, x)); z2 = __fadd_rn(z2, __fmul_rn(y, y));
            unpack2(a.y, x, y);
            z2 = __fadd_rn(z2, __fmul_rn(x, x)); z2 = __fadd_rn(z2, __fmul_rn(y, y));
        }
    }

    float best = 3.4e38f;
    int   bidx = 0;

    for (int t0 = 0; t0 < K; t0 += TK) {
        __syncthreads();
        {   // stage codebook tile (coalesced float4) + e2 slice; 2 warps share
            const float4* cp = reinterpret_cast<const float4*>(cb + (size_t)t0 * DIMS);
            float4* sp = reinterpret_cast<float4*>(s_tile);
#pragma unroll 8
            for (int i = threadIdx.x; i < TK * DIMS / 4; i += CTA) sp[i] = cp[i];
            s_e2[threadIdx.x]      = g_e2[t0 + threadIdx.x];
            s_e2[threadIdx.x + 64] = g_e2[t0 + threadIdx.x + 64];
        }
        __syncthreads();

#pragma unroll 4
        for (int kk = 0; kk < TK; kk++) {
            const ulonglong2* cs =
                reinterpret_cast<const ulonglong2*>(s_tile + kk * DIMS);
            const float e2  = s_e2[kk];
            const int  kidx = t0 + kk;

            u64 a0 = 0, a1 = 0, a2 = 0, a3 = 0;   // 4-acc tree (as R1)
#pragma unroll
            for (int j = 0; j < DIMS / 8; j++) {
                ulonglong2 c0 = cs[2 * j + 0];
                ulonglong2 c1 = cs[2 * j + 1];
                a0 = fma2(zr[4 * j + 0], c0.x, a0);
                a1 = fma2(zr[4 * j + 1], c0.y, a1);
                a2 = fma2(zr[4 * j + 2], c1.x, a2);
                a3 = fma2(zr[4 * j + 3], c1.y, a3);
            }
            u64 s = add2(add2(a0, a1), add2(a2, a3));
            float lo, hi;
            unpack2(s, lo, hi);
            float dot = __fadd_rn(lo, hi);
            float d = __fadd_rn(__fmaf_rn(-2.f, dot, z2), e2);
            bool lt = d < best;
            best = lt ? d    : best;
            bidx = lt ? kidx : bidx;
        }
    }

    if (act) {
        const float4* crow = reinterpret_cast<const float4*>(cb + (size_t)bidx * DIMS);
        float4* orow = reinterpret_cast<float4*>(out_q + (size_t)n0 * DIMS);
#pragma unroll
        for (int i = 0; i < DIMS / 4; i++) orow[i] = crow[i];
        if (out_idx) out_idx[n0] = (float)bidx;
    }
}

extern "C" void kernel_launch(void* const* d_in, const int* in_sizes, int n_in,
                              void* d_out, int out_size) {
    const float* z  = (const float*)d_in[0];
    const float* cb = (const float*)d_in[1];
    const int N = in_sizes[0] / DIMS;
    const int K = in_sizes[1] / DIMS;
    float* out = (float*)d_out;

    float* out_idx = nullptr;
    if ((long long)out_size >= (long long)N * DIMS + N)
        out_idx = out + (size_t)N * DIMS;

    e2_kernel<<<(K + 255) / 256, 256>>>(cb, K);
    vq_kernel<<<(N + CTA - 1) / CTA, CTA>>>(z, cb, N, K, out, out_idx);
}

// round 15
// speedup vs baseline: 1.2083x; 1.2059x over previous
#include <cuda_runtime.h>
#include <cstdint>

// VQ: argmin_k ||z_n - e_k||^2 -> z_q + indices. Scalar FFMA2 path.
// R15 = R10's grid balance (CTA=32, RPT=2, grid=1024, 98.8% util) fixed:
//   - TK=32 -> 8.4KB smem/CTA -> 10 CTAs (84KB) actually resident
//   - launch_bounds(32,10) -> 2.5 warps/SMSP (reg cap 204 > the ~196 needed)
//   - packed f32x2 epilogue from R9 (bit-identical lanes, fewer issues)
// Numerics byte-exact vs rel_err=0.0 kernels (4-acc tree, unfused z2/e2,
// d = fl(fmaf(-2,dot,z2)) + e2, tie keeps lowest index).

#define DIMS 64
#define TK   32      // codes per smem tile
#define CTA  32
#define RPT  2

__device__ float g_e2[8192];

typedef unsigned long long u64;

__device__ __forceinline__ u64 fma2(u64 a, u64 b, u64 c) {
    u64 r;
    asm("fma.rn.f32x2 %0, %1, %2, %3;" : "=l"(r) : "l"(a), "l"(b), "l"(c));
    return r;
}
__device__ __forceinline__ u64 add2(u64 a, u64 b) {
    u64 r;
    asm("add.rn.f32x2 %0, %1, %2;" : "=l"(r) : "l"(a), "l"(b));
    return r;
}
__device__ __forceinline__ void unpack2(u64 v, float& lo, float& hi) {
    asm("mov.b64 {%0, %1}, %2;" : "=f"(lo), "=f"(hi) : "l"(v));
}
__device__ __forceinline__ u64 pack2(float lo, float hi) {
    u64 r;
    asm("mov.b64 %0, {%1, %2};" : "=l"(r) : "f"(lo), "f"(hi));
    return r;
}

// ---- pass 1: ||e_k||^2 (reference order: square then add) --------------------
__global__ void e2_kernel(const float* __restrict__ cb, int K) {
    int k = blockIdx.x * blockDim.x + threadIdx.x;
    if (k >= K) return;
    const float4* row = reinterpret_cast<const float4*>(cb + (size_t)k * DIMS);
    float s = 0.f;
#pragma unroll
    for (int i = 0; i < DIMS / 4; i++) {
        float4 v = row[i];
        s = __fadd_rn(s, __fmul_rn(v.x, v.x));
        s = __fadd_rn(s, __fmul_rn(v.y, v.y));
        s = __fadd_rn(s, __fmul_rn(v.z, v.z));
        s = __fadd_rn(s, __fmul_rn(v.w, v.w));
    }
    g_e2[k] = s;
}

// ---- pass 2: main VQ ----------------------------------------------------------
__global__ __launch_bounds__(CTA, 10)
void vq_kernel(const float* __restrict__ z, const float* __restrict__ cb,
               int N, int K, float* __restrict__ out_q, float* __restrict__ out_idx)
{
    __shared__ float s_tile[TK * DIMS];
    __shared__ float s_e2[TK];

    const int n0 = blockIdx.x * (CTA * RPT) + threadIdx.x;
    const int n1 = n0 + CTA;
    const bool act0 = (n0 < N);
    const bool act1 = (n1 < N);

    // z rows in packed f32x2 registers (+ unfused ||z||^2, reference order)
    u64 zr0[DIMS / 2], zr1[DIMS / 2];
    float z20 = 0.f, z21 = 0.f;
    {
        const ulonglong2* zp0 = reinterpret_cast<const ulonglong2*>(z + (size_t)(act0 ? n0 : 0) * DIMS);
        const ulonglong2* zp1 = reinterpret_cast<const ulonglong2*>(z + (size_t)(act1 ? n1 : 0) * DIMS);
#pragma unroll
        for (int i = 0; i < DIMS / 4; i++) {
            ulonglong2 a = zp0[i];
            ulonglong2 b = zp1[i];
            zr0[2 * i + 0] = a.x; zr0[2 * i + 1] = a.y;
            zr1[2 * i + 0] = b.x; zr1[2 * i + 1] = b.y;
            float x, y;
            unpack2(a.x, x, y); z20 = __fadd_rn(z20, __fmul_rn(x, x)); z20 = __fadd_rn(z20, __fmul_rn(y, y));
            unpack2(a.y, x, y); z20 = __fadd_rn(z20, __fmul_rn(x, x)); z20 = __fadd_rn(z20, __fmul_rn(y, y));
            unpack2(b.x, x, y); z21 = __fadd_rn(z21, __fmul_rn(x, x)); z21 = __fadd_rn(z21, __fmul_rn(y, y));
            unpack2(b.y, x, y); z21 = __fadd_rn(z21, __fmul_rn(x, x)); z21 = __fadd_rn(z21, __fmul_rn(y, y));
        }
    }
    const u64 z2pair   = pack2(z20, z21);
    const u64 neg2pair = pack2(-2.f, -2.f);

    float best0 = 3.4e38f, best1 = 3.4e38f;
    int   bidx0 = 0,       bidx1 = 0;

    for (int t0 = 0; t0 < K; t0 += TK) {
        __syncwarp();
        {   // stage codebook tile (coalesced float4) + e2 slice; 1-warp CTA
            const float4* cp = reinterpret_cast<const float4*>(cb + (size_t)t0 * DIMS);
            float4* sp = reinterpret_cast<float4*>(s_tile);
#pragma unroll
            for (int i = threadIdx.x; i < TK * DIMS / 4; i += CTA) sp[i] = cp[i];
            s_e2[threadIdx.x] = g_e2[t0 + threadIdx.x];
        }
        __syncwarp();

#pragma unroll 2
        for (int kk = 0; kk < TK; kk++) {
            const ulonglong2* cs =
                reinterpret_cast<const ulonglong2*>(s_tile + kk * DIMS);
            const float e2  = s_e2[kk];
            const int  kidx = t0 + kk;

            u64 a0 = 0, a1 = 0, a2 = 0, a3 = 0;   // row0: 4-acc tree (as R1)
            u64 b0 = 0, b1 = 0, b2 = 0, b3 = 0;   // row1
#pragma unroll
            for (int j = 0; j < DIMS / 8; j++) {
                ulonglong2 c0 = cs[2 * j + 0];
                ulonglong2 c1 = cs[2 * j + 1];
                a0 = fma2(zr0[4 * j + 0], c0.x, a0);
                a1 = fma2(zr0[4 * j + 1], c0.y, a1);
                a2 = fma2(zr0[4 * j + 2], c1.x, a2);
                a3 = fma2(zr0[4 * j + 3], c1.y, a3);
                b0 = fma2(zr1[4 * j + 0], c0.x, b0);
                b1 = fma2(zr1[4 * j + 1], c0.y, b1);
                b2 = fma2(zr1[4 * j + 2], c1.x, b2);
                b3 = fma2(zr1[4 * j + 3], c1.y, b3);
            }
            // packed epilogue: each lane bit-identical to
            //   dot = fadd(lo,hi); d = fadd(fmaf(-2,dot,z2), e2)
            u64 sa = add2(add2(a0, a1), add2(a2, a3));
            u64 sb = add2(add2(b0, b1), add2(b2, b3));
            float al, ah, bl, bh;
            unpack2(sa, al, ah);
            unpack2(sb, bl, bh);
            u64 dot2 = add2(pack2(al, bl), pack2(ah, bh));    // (dot0, dot1)
            u64 tt   = fma2(neg2pair, dot2, z2pair);           // z2 - 2*dot
            u64 dd   = add2(tt, pack2(e2, e2));                // + e2
            float d0, d1;
            unpack2(dd, d0, d1);
            bool lt0 = d0 < best0;
            best0 = lt0 ? d0   : best0;
            bidx0 = lt0 ? kidx : bidx0;
            bool lt1 = d1 < best1;
            best1 = lt1 ? d1   : best1;
            bidx1 = lt1 ? kidx : bidx1;
        }
    }

    if (act0) {
        const float4* crow = reinterpret_cast<const float4*>(cb + (size_t)bidx0 * DIMS);
        float4* orow = reinterpret_cast<float4*>(out_q + (size_t)n0 * DIMS);
#pragma unroll
        for (int i = 0; i < DIMS / 4; i++) orow[i] = crow[i];
        if (out_idx) out_idx[n0] = (float)bidx0;
    }
    if (act1) {
        const float4* crow = reinterpret_cast<const float4*>(cb + (size_t)bidx1 * DIMS);
        float4* orow = reinterpret_cast<float4*>(out_q + (size_t)n1 * DIMS);
#pragma unroll
        for (int i = 0; i < DIMS / 4; i++) orow[i] = crow[i];
        if (out_idx) out_idx[n1] = (float)bidx1;
    }
}

extern "C" void kernel_launch(void* const* d_in, const int* in_sizes, int n_in,
                              void* d_out, int out_size) {
    const float* z  = (const float*)d_in[0];
    const float* cb = (const float*)d_in[1];
    const int N = in_sizes[0] / DIMS;
    const int K = in_sizes[1] / DIMS;
    float* out = (float*)d_out;

    float* out_idx = nullptr;
    if ((long long)out_size >= (long long)N * DIMS + N)
        out_idx = out + (size_t)N * DIMS;

    e2_kernel<<<(K + 255) / 256, 256>>>(cb, K);
    const int rows_per_block = CTA * RPT;   // 64
    vq_kernel<<<(N + rows_per_block - 1) / rows_per_block, CTA>>>(z, cb, N, K, out, out_idx);
}